// round 11
// baseline (speedup 1.0000x reference)
#include <cuda_runtime.h>
#include <cstdint>

#define BB 8

// Scratch
__device__ float2 g_X1[BB * 16 * 256 * 32];   // [b][k][y][c]
__device__ float2 g_OB[BB * 16 * 32 * 32];    // [bk][h'][o]  scaled einsum output
__device__ float2 g_G [BB * 256 * 16 * 32];   // [b][y][k][o]
__device__ float2 g_Wt[16 * 32 * 32 * 32];    // [k][h'][c][o]

// ---------------------------------------------------------------------------
// Compile-time trig table -> FFMA immediates after full unroll.
// ---------------------------------------------------------------------------
struct Trig { float c[256]; float s[256]; };

__host__ __device__ constexpr double tp_cos(double x) {
    double x2 = x * x, t = 1.0, s = 1.0;
    for (int n = 1; n <= 12; n++) { t *= -x2 / double((2 * n - 1) * (2 * n)); s += t; }
    return s;
}
__host__ __device__ constexpr double tp_sin(double x) {
    double x2 = x * x, t = x, s = x;
    for (int n = 1; n <= 12; n++) { t *= -x2 / double((2 * n) * (2 * n + 1)); s += t; }
    return s;
}
__host__ __device__ constexpr Trig make_trig() {
    Trig tr{};
    for (int i = 0; i < 256; i++) {
        int q = i >> 6, r = i & 63;
        double x = 3.14159265358979323846 * double(r) / 128.0;
        double c = tp_cos(x), s = tp_sin(x);
        tr.c[i] = (float)(q == 0 ? c : q == 1 ? -s : q == 2 ? -c :  s);
        tr.s[i] = (float)(q == 0 ? s : q == 1 ?  c : q == 2 ? -s : -c);
    }
    return tr;
}

#define SQ2H 0.70710678118654752440f

// ---------------------------------------------------------------------------
// k0: weight reorder (coalesced reads, scattered 8B stores).
// ---------------------------------------------------------------------------
__global__ void k0_reorder_w(const float* __restrict__ wr, const float* __restrict__ wi) {
    int idx = blockIdx.x * 256 + threadIdx.x;
    int m2 = idx & 15;
    int m1 = (idx >> 4) & 15;
    int o  = (idx >> 8) & 31;
    int c  = (idx >> 13) & 31;
    int w  = idx >> 18;
    int dst = ((m2 * 32 + (w * 16 + m1)) * 32 + c) * 32 + o;
    g_Wt[dst] = make_float2(wr[idx], wi[idx]);
}

// ---------------------------------------------------------------------------
// k1: forward W-DFT, 4-way x-symmetry (x, 256-x, 128-x, 128+x). One warp per
//   row; even/odd-k operand folding halves the FFMA count.
// ---------------------------------------------------------------------------
__global__ void __launch_bounds__(256) k1_fwd_w(const float* __restrict__ x) {
    constexpr Trig TR = make_trig();
    int t = threadIdx.x, c = t & 31;
    int row = blockIdx.x * 8 + (t >> 5);
    const float* __restrict__ p = x + (size_t)row * 8192 + c;

    float re[16], im[16];
    float v0 = p[0], v64 = p[64 * 32], v128 = p[128 * 32], v192 = p[192 * 32];
    float pe = v0 + v128, po = v0 - v128;
    float s64 = v64 + v192, d64 = v64 - v192;
#pragma unroll
    for (int k = 0; k < 16; k++) {
        re[k] = (k & 1) ? po : pe;
        im[k] = 0.f;
        // x = 64 / 192 edge: cos(k*pi/2), sin(k*pi/2) in {0,+-1}
        if ((k & 3) == 0) re[k] += s64;
        if ((k & 3) == 2) re[k] -= s64;
        if ((k & 3) == 1) im[k] -= d64;
        if ((k & 3) == 3) im[k] += d64;
    }

#pragma unroll
    for (int xp = 1; xp <= 63; xp++) {
        float a  = p[xp * 32];
        float b  = p[(256 - xp) * 32];
        float fm = p[(128 - xp) * 32];
        float fp = p[(128 + xp) * 32];
        float s1 = a + b,  s2 = fm + fp;
        float d1 = a - b,  d2 = fp - fm;
        float se = s1 + s2, so = s1 - s2;
        float de = d1 + d2, dd = d1 - d2;
#pragma unroll
        for (int k = 0; k < 16; k++) {
            const int id = (k * xp) & 255;
            re[k] = fmaf((k & 1) ? so : se, TR.c[id], re[k]);
            if (k) im[k] = fmaf((k & 1) ? dd : de, -TR.s[id], im[k]);
        }
    }

    int b_ = row >> 8, y = row & 255;
    float2* o = g_X1 + ((size_t)(b_ * 16) * 256 + y) * 32 + c;
#pragma unroll
    for (int k = 0; k < 16; k++) o[(size_t)k * 8192] = make_float2(re[k], im[k]);
}

// ---------------------------------------------------------------------------
// k2ac: fused fwd-H + einsum, one block per bk. Warp w = y-chunk; identical
//   immediates for all warps; rotation by 8-entry table; smem reduce; einsum.
// ---------------------------------------------------------------------------
__global__ void __launch_bounds__(256) k2ac_mid() {
    constexpr Trig TR = make_trig();
    __shared__ float red[4 * 17 * 4 * 32];
    __shared__ float2 X2s[32 * 32];
    __shared__ float ct8[8], st8[8];

    int t = threadIdx.x, w = t >> 5, c = t & 31;
    int bk = blockIdx.x, k = bk & 15;

    if (t < 8) {
        const float cv[8] = {1.f, SQ2H, 0.f, -SQ2H, -1.f, -SQ2H, 0.f, SQ2H};
        const float sv[8] = {0.f, SQ2H, 1.f, SQ2H, 0.f, -SQ2H, -1.f, -SQ2H};
        ct8[t] = cv[t]; st8[t] = sv[t];
    }

    const float2* __restrict__ xp = g_X1 + (size_t)bk * 8192 + (size_t)w * 32 * 32 + c;
    float Ar[17], Ai[17], Br[17], Bi[17];
#pragma unroll
    for (int m = 0; m < 17; m++) { Ar[m] = Ai[m] = Br[m] = Bi[m] = 0.f; }
#pragma unroll
    for (int u = 0; u < 32; u++) {
        float2 v = xp[u * 32];
#pragma unroll
        for (int m = 0; m < 17; m++) {
            const int id = (m * u) & 255;
            Ar[m] = fmaf(v.x, TR.c[id], Ar[m]);
            Ai[m] = fmaf(v.y, TR.c[id], Ai[m]);
            if (m) {
                Br[m] = fmaf(v.x, TR.s[id], Br[m]);
                Bi[m] = fmaf(v.y, TR.s[id], Bi[m]);
            }
        }
    }
    __syncthreads();

    float pr[17], pi[17], qr[17], qi[17];
#pragma unroll
    for (int m = 0; m < 17; m++) {
        int i8 = (m * w) & 7;
        float cw = ct8[i8], sw = st8[i8];
        pr[m] = cw * Ar[m] - sw * Br[m];
        pi[m] = cw * Ai[m] - sw * Bi[m];
        qr[m] = sw * Ar[m] + cw * Br[m];
        qi[m] = sw * Ai[m] + cw * Bi[m];
    }

    float* rb = red + (size_t)(w & 3) * 2176;
    if (w < 4) {
#pragma unroll
        for (int m = 0; m < 17; m++) {
            rb[m * 128 +       c] = pr[m];
            rb[m * 128 +  32 + c] = pi[m];
            rb[m * 128 +  64 + c] = qr[m];
            rb[m * 128 +  96 + c] = qi[m];
        }
    }
    __syncthreads();
    if (w >= 4) {
#pragma unroll
        for (int m = 0; m < 17; m++) {
            rb[m * 128 +       c] += pr[m];
            rb[m * 128 +  32 + c] += pi[m];
            rb[m * 128 +  64 + c] += qr[m];
            rb[m * 128 +  96 + c] += qi[m];
        }
    }
    __syncthreads();
#pragma unroll
    for (int s = 0; s < 2176; s += 256) {
        int ss = s + t;
        if (ss < 2176)
            red[ss] = red[ss] + red[ss + 2176] + red[ss + 2 * 2176] + red[ss + 3 * 2176];
    }
    __syncthreads();

#pragma unroll
    for (int idx = 0; idx < 1024; idx += 256) {
        int ii = idx + t;
        int h = ii >> 5, cc = ii & 31;
        int m = (h <= 15) ? h : (32 - h);
        if (h == 16) m = 16;
        float Pr = red[m * 128 + cc],      Pi = red[m * 128 + 32 + cc];
        float Qr = red[m * 128 + 64 + cc], Qi = red[m * 128 + 96 + cc];
        if (h <= 15) X2s[ii] = make_float2(Pr + Qi, Pi - Qr);
        else         X2s[ii] = make_float2(Pr - Qi, Pi + Qr);
    }
    __syncthreads();

    float sc = (k == 0) ? (1.0f / 65536.0f) : (2.0f / 65536.0f);
    const float2* __restrict__ wtk = g_Wt + (size_t)k * 32768;
#pragma unroll
    for (int j = 0; j < 4; j++) {
        int h = w * 4 + j;
        float ar = 0.f, ai = 0.f;
        const float2* __restrict__ xr = X2s + h * 32;
        const float2* __restrict__ wrow = wtk + (size_t)h * 1024 + c;
#pragma unroll
        for (int cc = 0; cc < 32; cc++) {
            float2 xx = xr[cc];
            float2 ww = wrow[cc * 32];
            ar = fmaf(xx.x, ww.x, ar); ar = fmaf(-xx.y, ww.y, ar);
            ai = fmaf(xx.x, ww.y, ai); ai = fmaf( xx.y, ww.x, ai);
        }
        g_OB[(size_t)bk * 1024 + h * 32 + c] = make_float2(ar * sc, ai * sc);
    }
}

// ---------------------------------------------------------------------------
// k2b: inverse H via chunk rotation. Grid 256 = (bk, half); block 256 = 8
//   warps = (e, qq); q = half*4 + qq. Single code region for all warps.
// ---------------------------------------------------------------------------
__global__ void __launch_bounds__(256) k2b_invh() {
    constexpr Trig TR = make_trig();
    __shared__ float ct8[8], st8[8];
    int t = threadIdx.x, w = t >> 5, o = t & 31;
    int e = w & 1, q = (blockIdx.x & 1) * 4 + (w >> 1);
    int bk = blockIdx.x >> 1, b = bk >> 4, k = bk & 15;

    if (t < 8) {
        const float cv[8] = {1.f, SQ2H, 0.f, -SQ2H, -1.f, -SQ2H, 0.f, SQ2H};
        const float sv[8] = {0.f, SQ2H, 1.f, SQ2H, 0.f, -SQ2H, -1.f, -SQ2H};
        ct8[t] = cv[t]; st8[t] = sv[t];
    }
    __syncthreads();

    const float2* __restrict__ ob = g_OB + (size_t)bk * 1024 + o;
    float a[17], bb[17];
#pragma unroll
    for (int p = 0; p < 17; p++) {
        float Urx = 0.f, Ury = 0.f, Vrx = 0.f, Vry = 0.f;
        if (p <= 15) { float2 U = ob[p * 32]; Urx = U.x; Ury = U.y; }
        if (p >= 1)  { float2 V = ob[(p == 16 ? 16 : 32 - p) * 32]; Vrx = V.x; Vry = V.y; }
        if (e == 0) { a[p] = Urx + Vrx; bb[p] = Vry - Ury; }
        else        { a[p] = Ury + Vry; bb[p] = Urx - Vrx; }
    }

#pragma unroll
    for (int p = 0; p < 17; p++) {
        int i8 = (p * q) & 7;
        float cq = ct8[i8], sq = st8[i8];
        float al = a[p] * cq + bb[p] * sq;
        float be = bb[p] * cq - a[p] * sq;
        a[p] = al; bb[p] = be;
    }

    float* __restrict__ gf = (float*)g_G + ((size_t)b * 262144 + (size_t)k * 64 + o * 2 + e)
                             + (size_t)(q * 32) * 1024;
#pragma unroll
    for (int u = 0; u < 32; u++) {
        float val = a[0];
#pragma unroll
        for (int p = 1; p < 17; p++) {
            const int id = (p * u) & 255;
            val = fmaf(a[p],  TR.c[id], val);
            val = fmaf(bb[p], TR.s[id], val);
        }
        gf[(size_t)u * 1024] = val;
    }
}

// ---------------------------------------------------------------------------
// k3: inverse W, 4-way x-symmetry. One warp per row; even/odd-k accumulators
//   give outputs at x, 256-x, 128-x, 128+x from one immediate sweep.
// ---------------------------------------------------------------------------
__global__ void __launch_bounds__(256) k3_inv_w(float* __restrict__ out) {
    constexpr Trig TR = make_trig();
    int t = threadIdx.x, o = t & 31;
    int row = blockIdx.x * 8 + (t >> 5);
    const float2* __restrict__ g = g_G + (size_t)row * 512 + o;

    float Gr[16], Gi[16];
#pragma unroll
    for (int k = 0; k < 16; k++) { float2 v = g[k * 32]; Gr[k] = v.x; Gi[k] = v.y; }

    float* __restrict__ ob = out + (size_t)row * 8192 + o;
#pragma unroll
    for (int xp = 0; xp <= 64; xp++) {
        float Ae = 0.f, Ao = 0.f, Be = 0.f, Bo = 0.f;
#pragma unroll
        for (int k = 0; k < 16; k++) {
            const int id = (k * xp) & 255;
            if (k & 1) Ao = fmaf(Gr[k], TR.c[id], Ao);
            else       Ae = fmaf(Gr[k], TR.c[id], Ae);
            if (k) {
                if (k & 1) Bo = fmaf(Gi[k], TR.s[id], Bo);
                else       Be = fmaf(Gi[k], TR.s[id], Be);
            }
        }
        float As = Ae + Ao, Ad = Ae - Ao;
        float Bs = Be + Bo, Bd = Be - Bo;
        ob[xp * 32] = As - Bs;                                    // x
        if (xp != 0 && xp != 64) {
            ob[(256 - xp) * 32] = As + Bs;                        // 256-x
            ob[(128 - xp) * 32] = Ad + Bd;                        // 128-x
        }
        if (xp != 64)
            ob[(128 + xp) * 32] = Ad - Bd;                        // 128+x
        if (xp == 64)
            ob[192 * 32] = As + Bs;                               // 256-64
    }
}

// ---------------------------------------------------------------------------
extern "C" void kernel_launch(void* const* d_in, const int* in_sizes, int n_in,
                              void* d_out, int out_size) {
    const float* x  = (const float*)d_in[0];
    const float* wr = (const float*)d_in[1];
    const float* wi = (const float*)d_in[2];
    float* out = (float*)d_out;

    k1_fwd_w    <<<256, 256>>>(x);
    k0_reorder_w<<<2048, 256>>>(wr, wi);   // g_Wt into L2 just before k2ac
    k2ac_mid    <<<128, 256>>>();
    k2b_invh    <<<256, 256>>>();
    k3_inv_w    <<<256, 256>>>(out);
}

// round 12
// speedup vs baseline: 1.2311x; 1.2311x over previous
#include <cuda_runtime.h>
#include <cstdint>

#define BB 8

// Scratch
__device__ float2 g_X1[BB * 16 * 256 * 32];   // [b][k][y][c]
__device__ float2 g_OB[BB * 16 * 32 * 32];    // [bk][h'][o]  scaled einsum output
__device__ float2 g_G [BB * 256 * 16 * 32];   // [b][y][k][o]
__device__ float2 g_Wt[16 * 32 * 32 * 32];    // [k][h'][c][o]

// ---------------------------------------------------------------------------
// Compile-time trig table -> FFMA immediates after full unroll.
// ---------------------------------------------------------------------------
struct Trig { float c[256]; float s[256]; };

__host__ __device__ constexpr double tp_cos(double x) {
    double x2 = x * x, t = 1.0, s = 1.0;
    for (int n = 1; n <= 12; n++) { t *= -x2 / double((2 * n - 1) * (2 * n)); s += t; }
    return s;
}
__host__ __device__ constexpr double tp_sin(double x) {
    double x2 = x * x, t = x, s = x;
    for (int n = 1; n <= 12; n++) { t *= -x2 / double((2 * n) * (2 * n + 1)); s += t; }
    return s;
}
__host__ __device__ constexpr Trig make_trig() {
    Trig tr{};
    for (int i = 0; i < 256; i++) {
        int q = i >> 6, r = i & 63;
        double x = 3.14159265358979323846 * double(r) / 128.0;
        double c = tp_cos(x), s = tp_sin(x);
        tr.c[i] = (float)(q == 0 ? c : q == 1 ? -s : q == 2 ? -c :  s);
        tr.s[i] = (float)(q == 0 ? s : q == 1 ?  c : q == 2 ? -s : -c);
    }
    return tr;
}

#define SQ2H 0.70710678118654752440f

// ---------------------------------------------------------------------------
// k0: weight reorder (coalesced reads, scattered 8B stores).
// ---------------------------------------------------------------------------
__global__ void k0_reorder_w(const float* __restrict__ wr, const float* __restrict__ wi) {
    int idx = blockIdx.x * 256 + threadIdx.x;
    int m2 = idx & 15;
    int m1 = (idx >> 4) & 15;
    int o  = (idx >> 8) & 31;
    int c  = (idx >> 13) & 31;
    int w  = idx >> 18;
    int dst = ((m2 * 32 + (w * 16 + m1)) * 32 + c) * 32 + o;
    g_Wt[dst] = make_float2(wr[idx], wi[idx]);
}

// ---------------------------------------------------------------------------
// k1: forward W-DFT. One warp per row, all 16 k-bins in registers.
//     (round-8 version: best measured; 16 independent FMA chains)
// ---------------------------------------------------------------------------
__global__ void __launch_bounds__(256) k1_fwd_w(const float* __restrict__ x) {
    constexpr Trig TR = make_trig();
    int t = threadIdx.x, c = t & 31;
    int row = blockIdx.x * 8 + (t >> 5);
    const float* __restrict__ p = x + (size_t)row * 8192 + c;

    float re[16], im[16];
    float v0 = p[0], v128 = p[128 * 32];
    float pe = v0 + v128, po = v0 - v128;
#pragma unroll
    for (int k = 0; k < 16; k++) { re[k] = (k & 1) ? po : pe; im[k] = 0.f; }

#pragma unroll
    for (int xp = 1; xp <= 127; xp++) {
        float a = p[xp * 32];
        float b = p[(256 - xp) * 32];
        float s = a + b, d = a - b;
#pragma unroll
        for (int k = 0; k < 16; k++) {
            const int id = (k * xp) & 255;
            re[k] = fmaf(s, TR.c[id], re[k]);
            if (k) im[k] = fmaf(d, -TR.s[id], im[k]);
        }
    }

    int b_ = row >> 8, y = row & 255;
    float2* o = g_X1 + ((size_t)(b_ * 16) * 256 + y) * 32 + c;
#pragma unroll
    for (int k = 0; k < 16; k++) o[(size_t)k * 8192] = make_float2(re[k], im[k]);
}

// ---------------------------------------------------------------------------
// k2ac: fused fwd-H + einsum, one block per bk. Warp w = y-chunk; identical
//   immediates for all warps; rotation by 8-entry table; smem reduce; einsum.
// ---------------------------------------------------------------------------
__global__ void __launch_bounds__(256) k2ac_mid() {
    constexpr Trig TR = make_trig();
    __shared__ float red[4 * 17 * 4 * 32];
    __shared__ float2 X2s[32 * 32];
    __shared__ float ct8[8], st8[8];

    int t = threadIdx.x, w = t >> 5, c = t & 31;
    int bk = blockIdx.x, k = bk & 15;

    if (t < 8) {
        const float cv[8] = {1.f, SQ2H, 0.f, -SQ2H, -1.f, -SQ2H, 0.f, SQ2H};
        const float sv[8] = {0.f, SQ2H, 1.f, SQ2H, 0.f, -SQ2H, -1.f, -SQ2H};
        ct8[t] = cv[t]; st8[t] = sv[t];
    }

    const float2* __restrict__ xp = g_X1 + (size_t)bk * 8192 + (size_t)w * 32 * 32 + c;
    float Ar[17], Ai[17], Br[17], Bi[17];
#pragma unroll
    for (int m = 0; m < 17; m++) { Ar[m] = Ai[m] = Br[m] = Bi[m] = 0.f; }
#pragma unroll
    for (int u = 0; u < 32; u++) {
        float2 v = xp[u * 32];
#pragma unroll
        for (int m = 0; m < 17; m++) {
            const int id = (m * u) & 255;
            Ar[m] = fmaf(v.x, TR.c[id], Ar[m]);
            Ai[m] = fmaf(v.y, TR.c[id], Ai[m]);
            if (m) {
                Br[m] = fmaf(v.x, TR.s[id], Br[m]);
                Bi[m] = fmaf(v.y, TR.s[id], Bi[m]);
            }
        }
    }
    __syncthreads();

    float pr[17], pi[17], qr[17], qi[17];
#pragma unroll
    for (int m = 0; m < 17; m++) {
        int i8 = (m * w) & 7;
        float cw = ct8[i8], sw = st8[i8];
        pr[m] = cw * Ar[m] - sw * Br[m];
        pi[m] = cw * Ai[m] - sw * Bi[m];
        qr[m] = sw * Ar[m] + cw * Br[m];
        qi[m] = sw * Ai[m] + cw * Bi[m];
    }

    float* rb = red + (size_t)(w & 3) * 2176;
    if (w < 4) {
#pragma unroll
        for (int m = 0; m < 17; m++) {
            rb[m * 128 +       c] = pr[m];
            rb[m * 128 +  32 + c] = pi[m];
            rb[m * 128 +  64 + c] = qr[m];
            rb[m * 128 +  96 + c] = qi[m];
        }
    }
    __syncthreads();
    if (w >= 4) {
#pragma unroll
        for (int m = 0; m < 17; m++) {
            rb[m * 128 +       c] += pr[m];
            rb[m * 128 +  32 + c] += pi[m];
            rb[m * 128 +  64 + c] += qr[m];
            rb[m * 128 +  96 + c] += qi[m];
        }
    }
    __syncthreads();
#pragma unroll
    for (int s = 0; s < 2176; s += 256) {
        int ss = s + t;
        if (ss < 2176)
            red[ss] = red[ss] + red[ss + 2176] + red[ss + 2 * 2176] + red[ss + 3 * 2176];
    }
    __syncthreads();

#pragma unroll
    for (int idx = 0; idx < 1024; idx += 256) {
        int ii = idx + t;
        int h = ii >> 5, cc = ii & 31;
        int m = (h <= 15) ? h : (32 - h);
        if (h == 16) m = 16;
        float Pr = red[m * 128 + cc],      Pi = red[m * 128 + 32 + cc];
        float Qr = red[m * 128 + 64 + cc], Qi = red[m * 128 + 96 + cc];
        if (h <= 15) X2s[ii] = make_float2(Pr + Qi, Pi - Qr);
        else         X2s[ii] = make_float2(Pr - Qi, Pi + Qr);
    }
    __syncthreads();

    float sc = (k == 0) ? (1.0f / 65536.0f) : (2.0f / 65536.0f);
    const float2* __restrict__ wtk = g_Wt + (size_t)k * 32768;
#pragma unroll
    for (int j = 0; j < 4; j++) {
        int h = w * 4 + j;
        float ar = 0.f, ai = 0.f;
        const float2* __restrict__ xr = X2s + h * 32;
        const float2* __restrict__ wrow = wtk + (size_t)h * 1024 + c;
#pragma unroll
        for (int cc = 0; cc < 32; cc++) {
            float2 xx = xr[cc];
            float2 ww = wrow[cc * 32];
            ar = fmaf(xx.x, ww.x, ar); ar = fmaf(-xx.y, ww.y, ar);
            ai = fmaf(xx.x, ww.y, ai); ai = fmaf( xx.y, ww.x, ai);
        }
        g_OB[(size_t)bk * 1024 + h * 32 + c] = make_float2(ar * sc, ai * sc);
    }
}

// ---------------------------------------------------------------------------
// k2b: inverse H via chunk rotation. Block per bk, 16 warps = (e, q).
//   Inner sum split across 4 INDEPENDENT accumulators (chain 33 -> ~9 FMA).
// ---------------------------------------------------------------------------
__global__ void __launch_bounds__(512) k2b_invh() {
    constexpr Trig TR = make_trig();
    __shared__ float ct8[8], st8[8];
    int t = threadIdx.x, w = t >> 5, o = t & 31;
    int e = w & 1, q = w >> 1;
    int bk = blockIdx.x, b = bk >> 4, k = bk & 15;

    if (t < 8) {
        const float cv[8] = {1.f, SQ2H, 0.f, -SQ2H, -1.f, -SQ2H, 0.f, SQ2H};
        const float sv[8] = {0.f, SQ2H, 1.f, SQ2H, 0.f, -SQ2H, -1.f, -SQ2H};
        ct8[t] = cv[t]; st8[t] = sv[t];
    }
    __syncthreads();

    // a[p], b[p]: val(y) = sum_p a_p cos(p th) + b_p sin(p th)
    const float2* __restrict__ ob = g_OB + (size_t)bk * 1024 + o;
    float a[17], bb[17];
#pragma unroll
    for (int p = 0; p < 17; p++) {
        float Urx = 0.f, Ury = 0.f, Vrx = 0.f, Vry = 0.f;
        if (p <= 15) { float2 U = ob[p * 32]; Urx = U.x; Ury = U.y; }
        if (p >= 1)  { float2 V = ob[(p == 16 ? 16 : 32 - p) * 32]; Vrx = V.x; Vry = V.y; }
        if (e == 0) { a[p] = Urx + Vrx; bb[p] = Vry - Ury; }
        else        { a[p] = Ury + Vry; bb[p] = Urx - Vrx; }
    }

    // rotate by chunk q
#pragma unroll
    for (int p = 0; p < 17; p++) {
        int i8 = (p * q) & 7;
        float cq = ct8[i8], sq = st8[i8];
        float al = a[p] * cq + bb[p] * sq;
        float be = bb[p] * cq - a[p] * sq;
        a[p] = al; bb[p] = be;
    }

    float* __restrict__ gf = (float*)g_G + ((size_t)b * 262144 + (size_t)k * 64 + o * 2 + e)
                             + (size_t)(q * 32) * 1024;
#pragma unroll
    for (int u = 0; u < 32; u++) {
        float v0 = a[0], v1 = 0.f, v2 = 0.f, v3 = 0.f;
#pragma unroll
        for (int p = 1; p < 17; p++) {
            const int id = (p * u) & 255;
            switch (p & 3) {
                case 0: v0 = fmaf(a[p], TR.c[id], v0); v1 = fmaf(bb[p], TR.s[id], v1); break;
                case 1: v1 = fmaf(a[p], TR.c[id], v1); v2 = fmaf(bb[p], TR.s[id], v2); break;
                case 2: v2 = fmaf(a[p], TR.c[id], v2); v3 = fmaf(bb[p], TR.s[id], v3); break;
                default: v3 = fmaf(a[p], TR.c[id], v3); v0 = fmaf(bb[p], TR.s[id], v0); break;
            }
        }
        gf[(size_t)u * 1024] = (v0 + v1) + (v2 + v3);
    }
}

// ---------------------------------------------------------------------------
// k3: inverse W. Block parity selects xp-half (I$-uniform); warp selects row.
// ---------------------------------------------------------------------------
template<int X0, int X1>
__device__ __forceinline__ void invW(const float* __restrict__ Gr,
                                     const float* __restrict__ Gi,
                                     float* __restrict__ ob) {
    constexpr Trig TR = make_trig();
#pragma unroll
    for (int xp = X0; xp < X1; xp++) {
        float A = 0.f, B = 0.f;
#pragma unroll
        for (int k = 0; k < 16; k++) {
            const int id = (k * xp) & 255;
            A = fmaf(Gr[k], TR.c[id], A);
            if (k) B = fmaf(Gi[k], TR.s[id], B);
        }
        ob[xp * 32] = A - B;
        if (xp != 0 && xp != 128)
            ob[(256 - xp) * 32] = A + B;
    }
}

__global__ void __launch_bounds__(256) k3_inv_w(float* __restrict__ out) {
    int t = threadIdx.x, o = t & 31, w = t >> 5;
    int half = blockIdx.x & 1;
    int row = (blockIdx.x >> 1) * 8 + w;
    const float2* __restrict__ g = g_G + (size_t)row * 512 + o;

    float Gr[16], Gi[16];
#pragma unroll
    for (int k = 0; k < 16; k++) { float2 v = g[k * 32]; Gr[k] = v.x; Gi[k] = v.y; }

    float* __restrict__ ob = out + (size_t)row * 8192 + o;
    if (half == 0) invW<0, 65>(Gr, Gi, ob);
    else           invW<65, 129>(Gr, Gi, ob);
}

// ---------------------------------------------------------------------------
extern "C" void kernel_launch(void* const* d_in, const int* in_sizes, int n_in,
                              void* d_out, int out_size) {
    const float* x  = (const float*)d_in[0];
    const float* wr = (const float*)d_in[1];
    const float* wi = (const float*)d_in[2];
    float* out = (float*)d_out;

    k1_fwd_w    <<<256, 256>>>(x);
    k0_reorder_w<<<2048, 256>>>(wr, wi);   // g_Wt into L2 just before k2ac
    k2ac_mid    <<<128, 256>>>();
    k2b_invh    <<<128, 512>>>();
    k3_inv_w    <<<512, 256>>>(out);
}

// round 13
// speedup vs baseline: 1.2362x; 1.0041x over previous
#include <cuda_runtime.h>
#include <cstdint>

#define BB 8

// Scratch
__device__ float2 g_X1[BB * 16 * 256 * 32];   // [b][k][y][c]
__device__ float2 g_OB[BB * 16 * 32 * 32];    // [bk][h'][o]  scaled einsum output
__device__ float2 g_G [BB * 256 * 16 * 32];   // [b][y][k][o]
__device__ float2 g_Wt[16 * 32 * 32 * 32];    // [k][h'][c][o]

// ---------------------------------------------------------------------------
// Compile-time trig table -> FFMA immediates after full unroll.
// ---------------------------------------------------------------------------
struct Trig { float c[256]; float s[256]; };

__host__ __device__ constexpr double tp_cos(double x) {
    double x2 = x * x, t = 1.0, s = 1.0;
    for (int n = 1; n <= 12; n++) { t *= -x2 / double((2 * n - 1) * (2 * n)); s += t; }
    return s;
}
__host__ __device__ constexpr double tp_sin(double x) {
    double x2 = x * x, t = x, s = x;
    for (int n = 1; n <= 12; n++) { t *= -x2 / double((2 * n) * (2 * n + 1)); s += t; }
    return s;
}
__host__ __device__ constexpr Trig make_trig() {
    Trig tr{};
    for (int i = 0; i < 256; i++) {
        int q = i >> 6, r = i & 63;
        double x = 3.14159265358979323846 * double(r) / 128.0;
        double c = tp_cos(x), s = tp_sin(x);
        tr.c[i] = (float)(q == 0 ? c : q == 1 ? -s : q == 2 ? -c :  s);
        tr.s[i] = (float)(q == 0 ? s : q == 1 ?  c : q == 2 ? -s : -c);
    }
    return tr;
}

#define SQ2H 0.70710678118654752440f

// ---------------------------------------------------------------------------
// k0: weight reorder (coalesced reads, scattered 8B stores).
// ---------------------------------------------------------------------------
__global__ void k0_reorder_w(const float* __restrict__ wr, const float* __restrict__ wi) {
    int idx = blockIdx.x * 256 + threadIdx.x;
    int m2 = idx & 15;
    int m1 = (idx >> 4) & 15;
    int o  = (idx >> 8) & 31;
    int c  = (idx >> 13) & 31;
    int w  = idx >> 18;
    int dst = ((m2 * 32 + (w * 16 + m1)) * 32 + c) * 32 + o;
    g_Wt[dst] = make_float2(wr[idx], wi[idx]);
}

// ---------------------------------------------------------------------------
// k1: forward W-DFT. One warp per row, all 16 k-bins in registers.
//     (round-8 version: best measured; 16 independent FMA chains)
// ---------------------------------------------------------------------------
__global__ void __launch_bounds__(256) k1_fwd_w(const float* __restrict__ x) {
    constexpr Trig TR = make_trig();
    int t = threadIdx.x, c = t & 31;
    int row = blockIdx.x * 8 + (t >> 5);
    const float* __restrict__ p = x + (size_t)row * 8192 + c;

    float re[16], im[16];
    float v0 = p[0], v128 = p[128 * 32];
    float pe = v0 + v128, po = v0 - v128;
#pragma unroll
    for (int k = 0; k < 16; k++) { re[k] = (k & 1) ? po : pe; im[k] = 0.f; }

#pragma unroll
    for (int xp = 1; xp <= 127; xp++) {
        float a = p[xp * 32];
        float b = p[(256 - xp) * 32];
        float s = a + b, d = a - b;
#pragma unroll
        for (int k = 0; k < 16; k++) {
            const int id = (k * xp) & 255;
            re[k] = fmaf(s, TR.c[id], re[k]);
            if (k) im[k] = fmaf(d, -TR.s[id], im[k]);
        }
    }

    int b_ = row >> 8, y = row & 255;
    float2* o = g_X1 + ((size_t)(b_ * 16) * 256 + y) * 32 + c;
#pragma unroll
    for (int k = 0; k < 16; k++) o[(size_t)k * 8192] = make_float2(re[k], im[k]);
}

// ---------------------------------------------------------------------------
// k2ac: fused fwd-H + einsum, one block per bk. Warp w = y-chunk; identical
//   immediates for all warps; rotation by 8-entry table; smem reduce; einsum.
// ---------------------------------------------------------------------------
__global__ void __launch_bounds__(256) k2ac_mid() {
    constexpr Trig TR = make_trig();
    __shared__ float red[4 * 17 * 4 * 32];
    __shared__ float2 X2s[32 * 32];
    __shared__ float ct8[8], st8[8];

    int t = threadIdx.x, w = t >> 5, c = t & 31;
    int bk = blockIdx.x, k = bk & 15;

    if (t < 8) {
        const float cv[8] = {1.f, SQ2H, 0.f, -SQ2H, -1.f, -SQ2H, 0.f, SQ2H};
        const float sv[8] = {0.f, SQ2H, 1.f, SQ2H, 0.f, -SQ2H, -1.f, -SQ2H};
        ct8[t] = cv[t]; st8[t] = sv[t];
    }

    const float2* __restrict__ xp = g_X1 + (size_t)bk * 8192 + (size_t)w * 32 * 32 + c;
    float Ar[17], Ai[17], Br[17], Bi[17];
#pragma unroll
    for (int m = 0; m < 17; m++) { Ar[m] = Ai[m] = Br[m] = Bi[m] = 0.f; }
#pragma unroll
    for (int u = 0; u < 32; u++) {
        float2 v = xp[u * 32];
#pragma unroll
        for (int m = 0; m < 17; m++) {
            const int id = (m * u) & 255;
            Ar[m] = fmaf(v.x, TR.c[id], Ar[m]);
            Ai[m] = fmaf(v.y, TR.c[id], Ai[m]);
            if (m) {
                Br[m] = fmaf(v.x, TR.s[id], Br[m]);
                Bi[m] = fmaf(v.y, TR.s[id], Bi[m]);
            }
        }
    }
    __syncthreads();

    float pr[17], pi[17], qr[17], qi[17];
#pragma unroll
    for (int m = 0; m < 17; m++) {
        int i8 = (m * w) & 7;
        float cw = ct8[i8], sw = st8[i8];
        pr[m] = cw * Ar[m] - sw * Br[m];
        pi[m] = cw * Ai[m] - sw * Bi[m];
        qr[m] = sw * Ar[m] + cw * Br[m];
        qi[m] = sw * Ai[m] + cw * Bi[m];
    }

    float* rb = red + (size_t)(w & 3) * 2176;
    if (w < 4) {
#pragma unroll
        for (int m = 0; m < 17; m++) {
            rb[m * 128 +       c] = pr[m];
            rb[m * 128 +  32 + c] = pi[m];
            rb[m * 128 +  64 + c] = qr[m];
            rb[m * 128 +  96 + c] = qi[m];
        }
    }
    __syncthreads();
    if (w >= 4) {
#pragma unroll
        for (int m = 0; m < 17; m++) {
            rb[m * 128 +       c] += pr[m];
            rb[m * 128 +  32 + c] += pi[m];
            rb[m * 128 +  64 + c] += qr[m];
            rb[m * 128 +  96 + c] += qi[m];
        }
    }
    __syncthreads();
#pragma unroll
    for (int s = 0; s < 2176; s += 256) {
        int ss = s + t;
        if (ss < 2176)
            red[ss] = red[ss] + red[ss + 2176] + red[ss + 2 * 2176] + red[ss + 3 * 2176];
    }
    __syncthreads();

#pragma unroll
    for (int idx = 0; idx < 1024; idx += 256) {
        int ii = idx + t;
        int h = ii >> 5, cc = ii & 31;
        int m = (h <= 15) ? h : (32 - h);
        if (h == 16) m = 16;
        float Pr = red[m * 128 + cc],      Pi = red[m * 128 + 32 + cc];
        float Qr = red[m * 128 + 64 + cc], Qi = red[m * 128 + 96 + cc];
        if (h <= 15) X2s[ii] = make_float2(Pr + Qi, Pi - Qr);
        else         X2s[ii] = make_float2(Pr - Qi, Pi + Qr);
    }
    __syncthreads();

    float sc = (k == 0) ? (1.0f / 65536.0f) : (2.0f / 65536.0f);
    const float2* __restrict__ wtk = g_Wt + (size_t)k * 32768;
#pragma unroll
    for (int j = 0; j < 4; j++) {
        int h = w * 4 + j;
        float ar = 0.f, ai = 0.f;
        const float2* __restrict__ xr = X2s + h * 32;
        const float2* __restrict__ wrow = wtk + (size_t)h * 1024 + c;
#pragma unroll
        for (int cc = 0; cc < 32; cc++) {
            float2 xx = xr[cc];
            float2 ww = wrow[cc * 32];
            ar = fmaf(xx.x, ww.x, ar); ar = fmaf(-xx.y, ww.y, ar);
            ai = fmaf(xx.x, ww.y, ai); ai = fmaf( xx.y, ww.x, ai);
        }
        g_OB[(size_t)bk * 1024 + h * 32 + c] = make_float2(ar * sc, ai * sc);
    }
}

// ---------------------------------------------------------------------------
// k2b: inverse H via chunk rotation. Block per bk, 16 warps = (e, q).
//   Inner sum split across 4 INDEPENDENT accumulators (chain 33 -> ~9 FMA).
// ---------------------------------------------------------------------------
__global__ void __launch_bounds__(512) k2b_invh() {
    constexpr Trig TR = make_trig();
    __shared__ float ct8[8], st8[8];
    int t = threadIdx.x, w = t >> 5, o = t & 31;
    int e = w & 1, q = w >> 1;
    int bk = blockIdx.x, b = bk >> 4, k = bk & 15;

    if (t < 8) {
        const float cv[8] = {1.f, SQ2H, 0.f, -SQ2H, -1.f, -SQ2H, 0.f, SQ2H};
        const float sv[8] = {0.f, SQ2H, 1.f, SQ2H, 0.f, -SQ2H, -1.f, -SQ2H};
        ct8[t] = cv[t]; st8[t] = sv[t];
    }
    __syncthreads();

    // a[p], b[p]: val(y) = sum_p a_p cos(p th) + b_p sin(p th)
    const float2* __restrict__ ob = g_OB + (size_t)bk * 1024 + o;
    float a[17], bb[17];
#pragma unroll
    for (int p = 0; p < 17; p++) {
        float Urx = 0.f, Ury = 0.f, Vrx = 0.f, Vry = 0.f;
        if (p <= 15) { float2 U = ob[p * 32]; Urx = U.x; Ury = U.y; }
        if (p >= 1)  { float2 V = ob[(p == 16 ? 16 : 32 - p) * 32]; Vrx = V.x; Vry = V.y; }
        if (e == 0) { a[p] = Urx + Vrx; bb[p] = Vry - Ury; }
        else        { a[p] = Ury + Vry; bb[p] = Urx - Vrx; }
    }

    // rotate by chunk q
#pragma unroll
    for (int p = 0; p < 17; p++) {
        int i8 = (p * q) & 7;
        float cq = ct8[i8], sq = st8[i8];
        float al = a[p] * cq + bb[p] * sq;
        float be = bb[p] * cq - a[p] * sq;
        a[p] = al; bb[p] = be;
    }

    float* __restrict__ gf = (float*)g_G + ((size_t)b * 262144 + (size_t)k * 64 + o * 2 + e)
                             + (size_t)(q * 32) * 1024;
#pragma unroll
    for (int u = 0; u < 32; u++) {
        float v0 = a[0], v1 = 0.f, v2 = 0.f, v3 = 0.f;
#pragma unroll
        for (int p = 1; p < 17; p++) {
            const int id = (p * u) & 255;
            switch (p & 3) {
                case 0: v0 = fmaf(a[p], TR.c[id], v0); v1 = fmaf(bb[p], TR.s[id], v1); break;
                case 1: v1 = fmaf(a[p], TR.c[id], v1); v2 = fmaf(bb[p], TR.s[id], v2); break;
                case 2: v2 = fmaf(a[p], TR.c[id], v2); v3 = fmaf(bb[p], TR.s[id], v3); break;
                default: v3 = fmaf(a[p], TR.c[id], v3); v0 = fmaf(bb[p], TR.s[id], v0); break;
            }
        }
        gf[(size_t)u * 1024] = (v0 + v1) + (v2 + v3);
    }
}

// ---------------------------------------------------------------------------
// k3: inverse W. Block parity selects xp-half (I$-uniform); warp selects row.
// ---------------------------------------------------------------------------
template<int X0, int X1>
__device__ __forceinline__ void invW(const float* __restrict__ Gr,
                                     const float* __restrict__ Gi,
                                     float* __restrict__ ob) {
    constexpr Trig TR = make_trig();
#pragma unroll
    for (int xp = X0; xp < X1; xp++) {
        float A = 0.f, B = 0.f;
#pragma unroll
        for (int k = 0; k < 16; k++) {
            const int id = (k * xp) & 255;
            A = fmaf(Gr[k], TR.c[id], A);
            if (k) B = fmaf(Gi[k], TR.s[id], B);
        }
        ob[xp * 32] = A - B;
        if (xp != 0 && xp != 128)
            ob[(256 - xp) * 32] = A + B;
    }
}

__global__ void __launch_bounds__(256) k3_inv_w(float* __restrict__ out) {
    int t = threadIdx.x, o = t & 31, w = t >> 5;
    int half = blockIdx.x & 1;
    int row = (blockIdx.x >> 1) * 8 + w;
    const float2* __restrict__ g = g_G + (size_t)row * 512 + o;

    float Gr[16], Gi[16];
#pragma unroll
    for (int k = 0; k < 16; k++) { float2 v = g[k * 32]; Gr[k] = v.x; Gi[k] = v.y; }

    float* __restrict__ ob = out + (size_t)row * 8192 + o;
    if (half == 0) invW<0, 65>(Gr, Gi, ob);
    else           invW<65, 129>(Gr, Gi, ob);
}

// ---------------------------------------------------------------------------
extern "C" void kernel_launch(void* const* d_in, const int* in_sizes, int n_in,
                              void* d_out, int out_size) {
    const float* x  = (const float*)d_in[0];
    const float* wr = (const float*)d_in[1];
    const float* wi = (const float*)d_in[2];
    float* out = (float*)d_out;

    k1_fwd_w    <<<256, 256>>>(x);
    k0_reorder_w<<<2048, 256>>>(wr, wi);   // g_Wt into L2 just before k2ac
    k2ac_mid    <<<128, 256>>>();
    k2b_invh    <<<128, 512>>>();
    k3_inv_w    <<<512, 256>>>(out);
}